// round 1
// baseline (speedup 1.0000x reference)
#include <cuda_runtime.h>

// ---------------------------------------------------------------------------
// XPool cross-modal attention, GB300 round 1: all-fp32, GEMM-ified.
//
// Shapes: text tokens M=4096 (128*32), video tokens 768 (64*12), E=512,
// H=2 heads x D=256. Heads are contiguous 256-col slices of E.
//
// Pipeline:
//   tn = LN1(text)            [4096,512]
//   vn = LN1(video)           [768,512]
//   Q = tn @ Wq^T + bq        [4096,512]     (NT gemm)
//   K = vn @ Wk^T + bk        [768,512]
//   V = vn @ Wv^T + bv        [768,512]
//   S_h = Q_h @ K_h^T / 16    [4096,768] per head   (NT gemm, K=256)
//   P = softmax over each 12-col group of S  (per-video frame softmax)
//   attn_h = P_h @ V_h / 64   [4096,256] per head   (NN gemm; mean over
//                              videos == concatenated GEMM * 1/64)
//   opre = attn @ Wo^T + bo ; o = LN2(opre)
//   lin  = o @ Wl^T + bl    ; out = LN3(o + lin)
// ---------------------------------------------------------------------------

#define EMBED 512
#define HEADS 2
#define HDIM  256
#define TTOK  4096
#define VTOK  768
#define FR    12
#define NV    64

// Scratch (device globals: allocation-free per harness rules)
__device__ float g_tn  [TTOK*EMBED];
__device__ float g_vn  [VTOK*EMBED];
__device__ float g_q   [TTOK*EMBED];
__device__ float g_k   [VTOK*EMBED];
__device__ float g_v   [VTOK*EMBED];
__device__ float g_s   [HEADS*TTOK*VTOK];
__device__ float g_attn[TTOK*EMBED];
__device__ float g_opre[TTOK*EMBED];
__device__ float g_o   [TTOK*EMBED];
__device__ float g_lin [TTOK*EMBED];

// ---------------------------------------------------------------------------
// LayerNorm over last dim (512). One block per row, 128 threads x 4 elems.
// If addx != nullptr, normalizes (x + addx) (residual fusion for LN3).
// ---------------------------------------------------------------------------
__global__ __launch_bounds__(128) void ln_kernel(
    const float* __restrict__ x, const float* __restrict__ addx,
    const float* __restrict__ g, const float* __restrict__ b,
    float* __restrict__ out)
{
    const int row = blockIdx.x;
    const int t = threadIdx.x;
    const float* xr = x + (size_t)row * EMBED;

    float v[4];
#pragma unroll
    for (int i = 0; i < 4; i++) {
        float val = xr[t + i * 128];
        if (addx) val += addx[(size_t)row * EMBED + t + i * 128];
        v[i] = val;
    }
    float s  = v[0] + v[1] + v[2] + v[3];
    float s2 = v[0]*v[0] + v[1]*v[1] + v[2]*v[2] + v[3]*v[3];
#pragma unroll
    for (int o = 16; o > 0; o >>= 1) {
        s  += __shfl_xor_sync(0xffffffffu, s,  o);
        s2 += __shfl_xor_sync(0xffffffffu, s2, o);
    }
    __shared__ float ss[4], ss2[4];
    const int w = t >> 5, l = t & 31;
    if (l == 0) { ss[w] = s; ss2[w] = s2; }
    __syncthreads();
    s  = ss[0] + ss[1] + ss[2] + ss[3];
    s2 = ss2[0] + ss2[1] + ss2[2] + ss2[3];

    const float mu   = s * (1.0f / EMBED);
    const float var  = s2 * (1.0f / EMBED) - mu * mu;
    const float rstd = rsqrtf(var + 1e-5f);
#pragma unroll
    for (int i = 0; i < 4; i++) {
        const int c = t + i * 128;
        out[(size_t)row * EMBED + c] = (v[i] - mu) * rstd * g[c] + b[c];
    }
}

// ---------------------------------------------------------------------------
// SGEMM: 128x128x8 tiles, 256 threads, 8x8 per thread, padded smem.
// MODE 0 (NT): C[i,j] = sum_k A[i*lda+k] * B[j*ldb+k]
// MODE 1 (NN): C[i,j] = sum_k A[i*lda+k] * B[k*ldb+j]
// C = alpha * acc + (bias ? bias[j] : 0). All dims divisible by tiles.
// ---------------------------------------------------------------------------
template <int MODE>
__global__ __launch_bounds__(256) void gemm_kernel(
    const float* __restrict__ A, int lda,
    const float* __restrict__ B, int ldb,
    float* __restrict__ C, int ldc,
    const float* __restrict__ bias,
    float alpha, int K)
{
    __shared__ float As[8][132];   // +4 pad: conflict-free transposed stores
    __shared__ float Bs[8][132];

    const int tid = threadIdx.x;
    const int bm = blockIdx.y * 128;
    const int bn = blockIdx.x * 128;
    const int tx = tid & 15;       // 16 col-threads * 8 = 128 cols
    const int ty = tid >> 4;       // 16 row-threads * 8 = 128 rows

    const int ld_row = tid >> 1;          // 0..127
    const int ld_k   = (tid & 1) << 2;    // 0 or 4
    const int bk_row = tid >> 5;          // NN: 0..7
    const int bn_col = (tid & 31) << 2;   // NN: 0..124

    float acc[8][8];
#pragma unroll
    for (int i = 0; i < 8; i++)
#pragma unroll
        for (int j = 0; j < 8; j++) acc[i][j] = 0.0f;

    const float* Aptr = A + (size_t)(bm + ld_row) * lda + ld_k;
    const float* BptrNT = B + (size_t)(bn + ld_row) * ldb + ld_k;
    const float* BptrNN = B + (size_t)bk_row * ldb + bn + bn_col;

    for (int k0 = 0; k0 < K; k0 += 8) {
        float4 av = *(const float4*)(Aptr + k0);
        As[ld_k + 0][ld_row] = av.x;
        As[ld_k + 1][ld_row] = av.y;
        As[ld_k + 2][ld_row] = av.z;
        As[ld_k + 3][ld_row] = av.w;
        if (MODE == 0) {
            float4 bv = *(const float4*)(BptrNT + k0);
            Bs[ld_k + 0][ld_row] = bv.x;
            Bs[ld_k + 1][ld_row] = bv.y;
            Bs[ld_k + 2][ld_row] = bv.z;
            Bs[ld_k + 3][ld_row] = bv.w;
        } else {
            float4 bv = *(const float4*)(BptrNN + (size_t)k0 * ldb);
            *(float4*)&Bs[bk_row][bn_col] = bv;
        }
        __syncthreads();

#pragma unroll
        for (int kk = 0; kk < 8; kk++) {
            float ar[8], br[8];
            *(float4*)&ar[0] = *(const float4*)&As[kk][ty * 8];
            *(float4*)&ar[4] = *(const float4*)&As[kk][ty * 8 + 4];
            *(float4*)&br[0] = *(const float4*)&Bs[kk][tx * 8];
            *(float4*)&br[4] = *(const float4*)&Bs[kk][tx * 8 + 4];
#pragma unroll
            for (int i = 0; i < 8; i++)
#pragma unroll
                for (int j = 0; j < 8; j++)
                    acc[i][j] = fmaf(ar[i], br[j], acc[i][j]);
        }
        __syncthreads();
    }

#pragma unroll
    for (int i = 0; i < 8; i++) {
        const int r = bm + ty * 8 + i;
#pragma unroll
        for (int j = 0; j < 8; j += 4) {
            const int c = bn + tx * 8 + j;
            float4 o;
            o.x = alpha * acc[i][j + 0];
            o.y = alpha * acc[i][j + 1];
            o.z = alpha * acc[i][j + 2];
            o.w = alpha * acc[i][j + 3];
            if (bias) {
                o.x += bias[c + 0]; o.y += bias[c + 1];
                o.z += bias[c + 2]; o.w += bias[c + 3];
            }
            *(float4*)(C + (size_t)r * ldc + c) = o;
        }
    }
}

// ---------------------------------------------------------------------------
// Per-video frame softmax: groups of 12 contiguous floats, one per thread.
// ---------------------------------------------------------------------------
__global__ __launch_bounds__(256) void softmax_kernel(float* __restrict__ S, int ngroups)
{
    const int g = blockIdx.x * blockDim.x + threadIdx.x;
    if (g >= ngroups) return;
    float* p = S + (size_t)g * FR;
    float v[FR];
    float m = -3.0e38f;
#pragma unroll
    for (int i = 0; i < FR; i++) { v[i] = p[i]; m = fmaxf(m, v[i]); }
    float s = 0.0f;
#pragma unroll
    for (int i = 0; i < FR; i++) { v[i] = __expf(v[i] - m); s += v[i]; }
    const float inv = 1.0f / s;
#pragma unroll
    for (int i = 0; i < FR; i++) p[i] = v[i] * inv;
}

// ---------------------------------------------------------------------------
extern "C" void kernel_launch(void* const* d_in, const int* in_sizes, int n_in,
                              void* d_out, int out_size)
{
    const float* text  = (const float*)d_in[0];
    const float* video = (const float*)d_in[1];
    const float* ln1_g = (const float*)d_in[2];
    const float* ln1_b = (const float*)d_in[3];
    const float* Wq = (const float*)d_in[4];
    const float* bq = (const float*)d_in[5];
    const float* Wk = (const float*)d_in[6];
    const float* bk = (const float*)d_in[7];
    const float* Wv = (const float*)d_in[8];
    const float* bv = (const float*)d_in[9];
    const float* Wo = (const float*)d_in[10];
    const float* bo = (const float*)d_in[11];
    const float* Wl = (const float*)d_in[12];
    const float* bl = (const float*)d_in[13];
    const float* ln2_g = (const float*)d_in[14];
    const float* ln2_b = (const float*)d_in[15];
    const float* ln3_g = (const float*)d_in[16];
    const float* ln3_b = (const float*)d_in[17];
    float* out = (float*)d_out;

    float *tn, *vn, *q, *k, *v, *s, *attn, *opre, *o, *lin;
    cudaGetSymbolAddress((void**)&tn,   g_tn);
    cudaGetSymbolAddress((void**)&vn,   g_vn);
    cudaGetSymbolAddress((void**)&q,    g_q);
    cudaGetSymbolAddress((void**)&k,    g_k);
    cudaGetSymbolAddress((void**)&v,    g_v);
    cudaGetSymbolAddress((void**)&s,    g_s);
    cudaGetSymbolAddress((void**)&attn, g_attn);
    cudaGetSymbolAddress((void**)&opre, g_opre);
    cudaGetSymbolAddress((void**)&o,    g_o);
    cudaGetSymbolAddress((void**)&lin,  g_lin);

    // 1) shared LN1 on both modalities
    ln_kernel<<<TTOK, 128>>>(text,  nullptr, ln1_g, ln1_b, tn);
    ln_kernel<<<VTOK, 128>>>(video, nullptr, ln1_g, ln1_b, vn);

    // 2) projections (NT: weight rows are output features, K contiguous)
    gemm_kernel<0><<<dim3(4, 32), 256>>>(tn, EMBED, Wq, EMBED, q, EMBED, bq, 1.0f, EMBED);
    gemm_kernel<0><<<dim3(4, 6),  256>>>(vn, EMBED, Wk, EMBED, k, EMBED, bk, 1.0f, EMBED);
    gemm_kernel<0><<<dim3(4, 6),  256>>>(vn, EMBED, Wv, EMBED, v, EMBED, bv, 1.0f, EMBED);

    // 3) attention logits per head: S_h = Q_h @ K_h^T / sqrt(256)
    for (int h = 0; h < HEADS; h++) {
        gemm_kernel<0><<<dim3(6, 32), 256>>>(
            q + h * HDIM, EMBED, k + h * HDIM, EMBED,
            s + (size_t)h * TTOK * VTOK, VTOK, nullptr, 1.0f / 16.0f, HDIM);
    }

    // 4) per-(video,head,token) softmax over 12 frames
    softmax_kernel<<<(HEADS * TTOK * NV + 255) / 256, 256>>>(s, HEADS * TTOK * NV);

    // 5) attn_h = P_h @ V_h / 64  (mean over videos folded into alpha)
    for (int h = 0; h < HEADS; h++) {
        gemm_kernel<1><<<dim3(2, 32), 256>>>(
            s + (size_t)h * TTOK * VTOK, VTOK, v + h * HDIM, EMBED,
            attn + h * HDIM, EMBED, nullptr, 1.0f / 64.0f, VTOK);
    }

    // 6) output projection + LN2
    gemm_kernel<0><<<dim3(4, 32), 256>>>(attn, EMBED, Wo, EMBED, opre, EMBED, bo, 1.0f, EMBED);
    ln_kernel<<<TTOK, 128>>>(opre, nullptr, ln2_g, ln2_b, o);

    // 7) linear + residual + LN3 -> out
    gemm_kernel<0><<<dim3(4, 32), 256>>>(o, EMBED, Wl, EMBED, lin, EMBED, bl, 1.0f, EMBED);
    ln_kernel<<<TTOK, 128>>>(o, lin, ln3_g, ln3_b, out);
}

// round 3
// speedup vs baseline: 2.1435x; 2.1435x over previous
#include <cuda_runtime.h>
#include <cstdint>

// ---------------------------------------------------------------------------
// XPool cross-modal attention, GB300 round 3: mma.sync tf32 GEMMs.
// (tcgen05 PTX is rejected by this toolchain's compute_103 target; use the
//  family-portable mma.sync.m16n8k8 tf32 path instead.)
//
// One NT tf32 GEMM engine: C[i,j] = alpha * sum_k A[i,k]*B[j,k] (+bias[j])
// CTA = 128x128 tile, 4 warps x (64x64 warp tile), BK=16, double-buffered
// k-major SMEM, conflict-free fragment loads, fp32 accumulate.
// ---------------------------------------------------------------------------

#define EMBED 512
#define HEADS 2
#define HDIM  256
#define TTOK  4096
#define VTOK  768
#define FR    12
#define NV    64

// ------------------------------- scratch ----------------------------------
__device__ float g_tn  [TTOK*EMBED];
__device__ float g_vn  [VTOK*EMBED];
__device__ float g_q   [TTOK*EMBED];
__device__ float g_k   [VTOK*EMBED];
__device__ float g_v   [VTOK*EMBED];
__device__ float g_vt  [EMBED*VTOK];          // V transposed [512][768]
__device__ float g_s   [HEADS*TTOK*VTOK];     // logits/probs
__device__ float g_attn[TTOK*EMBED];
__device__ float g_opre[TTOK*EMBED];
__device__ float g_o   [TTOK*EMBED];
__device__ float g_lin [TTOK*EMBED];

__device__ __forceinline__ uint32_t f2tf32(float x) {
    uint32_t u;
    asm("cvt.rna.tf32.f32 %0, %1;" : "=r"(u) : "f"(x));
    return u;
}

// ---------------------------------------------------------------------------
// tf32 NT GEMM via mma.sync.m16n8k8.
// grid = (N/128, M/128, Z); 128 threads (4 warps, 2x2 of 64x64 warp tiles).
// ---------------------------------------------------------------------------
__global__ __launch_bounds__(128) void mma_gemm(
    const float* __restrict__ A, int lda, long zA,
    const float* __restrict__ B, int ldb, long zB,
    float* __restrict__ C, int ldc, long zC,
    const float* __restrict__ bias, float alpha, int K)
{
    // k-major tiles: As[buf][k][row], stride 132 -> bank = (4k + row) mod 32
    __shared__ uint32_t As[2][16][132];
    __shared__ uint32_t Bs[2][16][132];

    const int tid  = threadIdx.x;
    const int lane = tid & 31;
    const int warp = tid >> 5;
    const int wm   = (warp >> 1) * 64;   // warp row offset in tile
    const int wn   = (warp & 1) * 64;    // warp col offset in tile
    const int gid  = lane >> 2;          // group id 0..7
    const int tig  = lane & 3;           // thread-in-group 0..3

    const int bm = blockIdx.y * 128;
    const int bn = blockIdx.x * 128;
    A += (long)blockIdx.z * zA;
    B += (long)blockIdx.z * zB;
    C += (long)blockIdx.z * zC;

    const float* Ap = A + (size_t)(bm + tid) * lda;   // one row per thread
    const float* Bp = B + (size_t)(bn + tid) * ldb;

    float acc[4][8][4];
#pragma unroll
    for (int mi = 0; mi < 4; mi++)
#pragma unroll
        for (int ni = 0; ni < 8; ni++)
#pragma unroll
            for (int r = 0; r < 4; r++) acc[mi][ni][r] = 0.0f;

    const int nsteps = K / 16;

    // stage 0
    {
        float4 pa[4], pb[4];
#pragma unroll
        for (int j = 0; j < 4; j++) {
            pa[j] = *(const float4*)(Ap + j * 4);
            pb[j] = *(const float4*)(Bp + j * 4);
        }
#pragma unroll
        for (int j = 0; j < 4; j++) {
            As[0][j*4+0][tid] = f2tf32(pa[j].x);
            As[0][j*4+1][tid] = f2tf32(pa[j].y);
            As[0][j*4+2][tid] = f2tf32(pa[j].z);
            As[0][j*4+3][tid] = f2tf32(pa[j].w);
            Bs[0][j*4+0][tid] = f2tf32(pb[j].x);
            Bs[0][j*4+1][tid] = f2tf32(pb[j].y);
            Bs[0][j*4+2][tid] = f2tf32(pb[j].z);
            Bs[0][j*4+3][tid] = f2tf32(pb[j].w);
        }
    }
    __syncthreads();

#pragma unroll 1
    for (int step = 0; step < nsteps; step++) {
        const int cur = step & 1;
        const int nxt = cur ^ 1;
        const bool has_next = (step + 1) < nsteps;

        float4 pa[4], pb[4];
        if (has_next) {
            const float* ap = Ap + (step + 1) * 16;
            const float* bp = Bp + (step + 1) * 16;
#pragma unroll
            for (int j = 0; j < 4; j++) {
                pa[j] = *(const float4*)(ap + j * 4);
                pb[j] = *(const float4*)(bp + j * 4);
            }
        }

        // compute on buffer cur: 2 k-octets
#pragma unroll
        for (int kk = 0; kk < 2; kk++) {
            const int kb = kk * 8;
            uint32_t af[4][4];
#pragma unroll
            for (int mi = 0; mi < 4; mi++) {
                const int r0 = wm + mi * 16 + gid;
                af[mi][0] = As[cur][kb + tig    ][r0];
                af[mi][1] = As[cur][kb + tig    ][r0 + 8];
                af[mi][2] = As[cur][kb + tig + 4][r0];
                af[mi][3] = As[cur][kb + tig + 4][r0 + 8];
            }
            uint32_t bf[8][2];
#pragma unroll
            for (int ni = 0; ni < 8; ni++) {
                const int n0 = wn + ni * 8 + gid;
                bf[ni][0] = Bs[cur][kb + tig    ][n0];
                bf[ni][1] = Bs[cur][kb + tig + 4][n0];
            }
#pragma unroll
            for (int mi = 0; mi < 4; mi++)
#pragma unroll
                for (int ni = 0; ni < 8; ni++) {
                    asm("mma.sync.aligned.m16n8k8.row.col.f32.tf32.tf32.f32 "
                        "{%0,%1,%2,%3}, {%4,%5,%6,%7}, {%8,%9}, {%0,%1,%2,%3};"
                        : "+f"(acc[mi][ni][0]), "+f"(acc[mi][ni][1]),
                          "+f"(acc[mi][ni][2]), "+f"(acc[mi][ni][3])
                        : "r"(af[mi][0]), "r"(af[mi][1]),
                          "r"(af[mi][2]), "r"(af[mi][3]),
                          "r"(bf[ni][0]), "r"(bf[ni][1]));
                }
        }

        if (has_next) {
#pragma unroll
            for (int j = 0; j < 4; j++) {
                As[nxt][j*4+0][tid] = f2tf32(pa[j].x);
                As[nxt][j*4+1][tid] = f2tf32(pa[j].y);
                As[nxt][j*4+2][tid] = f2tf32(pa[j].z);
                As[nxt][j*4+3][tid] = f2tf32(pa[j].w);
                Bs[nxt][j*4+0][tid] = f2tf32(pb[j].x);
                Bs[nxt][j*4+1][tid] = f2tf32(pb[j].y);
                Bs[nxt][j*4+2][tid] = f2tf32(pb[j].z);
                Bs[nxt][j*4+3][tid] = f2tf32(pb[j].w);
            }
        }
        __syncthreads();
    }

    // epilogue: c0,c1 at (row, 2*tig), c2,c3 at (row+8, 2*tig)
#pragma unroll
    for (int mi = 0; mi < 4; mi++) {
        const int r0 = bm + wm + mi * 16 + gid;
#pragma unroll
        for (int ni = 0; ni < 8; ni++) {
            const int c0 = bn + wn + ni * 8 + tig * 2;
            float bx = 0.0f, by = 0.0f;
            if (bias) { bx = bias[c0]; by = bias[c0 + 1]; }
            float2 v0, v1;
            v0.x = alpha * acc[mi][ni][0] + bx;
            v0.y = alpha * acc[mi][ni][1] + by;
            v1.x = alpha * acc[mi][ni][2] + bx;
            v1.y = alpha * acc[mi][ni][3] + by;
            *(float2*)(C + (size_t)r0 * ldc + c0)       = v0;
            *(float2*)(C + (size_t)(r0 + 8) * ldc + c0) = v1;
        }
    }
}

// ---------------------------------------------------------------------------
// LayerNorm (optionally fused residual add). One block per row.
// ---------------------------------------------------------------------------
__global__ __launch_bounds__(128) void ln_kernel(
    const float* __restrict__ x, const float* __restrict__ addx,
    const float* __restrict__ g, const float* __restrict__ b,
    float* __restrict__ out)
{
    const int row = blockIdx.x;
    const int t = threadIdx.x;
    const float* xr = x + (size_t)row * EMBED;

    float v[4];
#pragma unroll
    for (int i = 0; i < 4; i++) {
        float val = xr[t + i * 128];
        if (addx) val += addx[(size_t)row * EMBED + t + i * 128];
        v[i] = val;
    }
    float s  = v[0] + v[1] + v[2] + v[3];
    float s2 = v[0]*v[0] + v[1]*v[1] + v[2]*v[2] + v[3]*v[3];
#pragma unroll
    for (int o = 16; o > 0; o >>= 1) {
        s  += __shfl_xor_sync(0xffffffffu, s,  o);
        s2 += __shfl_xor_sync(0xffffffffu, s2, o);
    }
    __shared__ float ss[4], ss2[4];
    const int w = t >> 5, l = t & 31;
    if (l == 0) { ss[w] = s; ss2[w] = s2; }
    __syncthreads();
    s  = ss[0] + ss[1] + ss[2] + ss[3];
    s2 = ss2[0] + ss2[1] + ss2[2] + ss2[3];

    const float mu   = s * (1.0f / EMBED);
    const float var  = s2 * (1.0f / EMBED) - mu * mu;
    const float rstd = rsqrtf(var + 1e-5f);
#pragma unroll
    for (int i = 0; i < 4; i++) {
        const int c = t + i * 128;
        out[(size_t)row * EMBED + c] = (v[i] - mu) * rstd * g[c] + b[c];
    }
}

// ---------------------------------------------------------------------------
// Per-(video,head,token) softmax over 12 contiguous frames.
// ---------------------------------------------------------------------------
__global__ __launch_bounds__(256) void softmax_kernel(float* __restrict__ S, int ngroups)
{
    const int g = blockIdx.x * blockDim.x + threadIdx.x;
    if (g >= ngroups) return;
    float* p = S + (size_t)g * FR;
    float v[FR];
    float m = -3.0e38f;
#pragma unroll
    for (int i = 0; i < FR; i++) { v[i] = p[i]; m = fmaxf(m, v[i]); }
    float sum = 0.0f;
#pragma unroll
    for (int i = 0; i < FR; i++) { v[i] = __expf(v[i] - m); sum += v[i]; }
    const float inv = 1.0f / sum;
#pragma unroll
    for (int i = 0; i < FR; i++) p[i] = v[i] * inv;
}

// ---------------------------------------------------------------------------
// Transpose V [768][512] -> Vt [512][768]
// ---------------------------------------------------------------------------
__global__ __launch_bounds__(256) void transpose_kernel(
    const float* __restrict__ in, float* __restrict__ out)
{
    __shared__ float t[32][33];
    const int x  = blockIdx.x * 32 + threadIdx.x;   // col in V (0..511)
    const int y0 = blockIdx.y * 32;                 // row in V (0..767)
#pragma unroll
    for (int i = threadIdx.y; i < 32; i += 8)
        t[i][threadIdx.x] = in[(size_t)(y0 + i) * EMBED + x];
    __syncthreads();
    const int ox  = y0 + threadIdx.x;               // col in Vt (0..767)
    const int oy0 = blockIdx.x * 32;                // row in Vt (0..511)
#pragma unroll
    for (int i = threadIdx.y; i < 32; i += 8)
        out[(size_t)(oy0 + i) * VTOK + ox] = t[threadIdx.x][i];
}

// ---------------------------------------------------------------------------
extern "C" void kernel_launch(void* const* d_in, const int* in_sizes, int n_in,
                              void* d_out, int out_size)
{
    const float* text  = (const float*)d_in[0];
    const float* video = (const float*)d_in[1];
    const float* ln1_g = (const float*)d_in[2];
    const float* ln1_b = (const float*)d_in[3];
    const float* Wq = (const float*)d_in[4];
    const float* bq = (const float*)d_in[5];
    const float* Wk = (const float*)d_in[6];
    const float* bk = (const float*)d_in[7];
    const float* Wv = (const float*)d_in[8];
    const float* bv = (const float*)d_in[9];
    const float* Wo = (const float*)d_in[10];
    const float* bo = (const float*)d_in[11];
    const float* Wl = (const float*)d_in[12];
    const float* bl = (const float*)d_in[13];
    const float* ln2_g = (const float*)d_in[14];
    const float* ln2_b = (const float*)d_in[15];
    const float* ln3_g = (const float*)d_in[16];
    const float* ln3_b = (const float*)d_in[17];
    float* out = (float*)d_out;

    float *tn, *vn, *q, *k, *v, *vt, *s, *attn, *opre, *o, *lin;
    cudaGetSymbolAddress((void**)&tn,   g_tn);
    cudaGetSymbolAddress((void**)&vn,   g_vn);
    cudaGetSymbolAddress((void**)&q,    g_q);
    cudaGetSymbolAddress((void**)&k,    g_k);
    cudaGetSymbolAddress((void**)&v,    g_v);
    cudaGetSymbolAddress((void**)&vt,   g_vt);
    cudaGetSymbolAddress((void**)&s,    g_s);
    cudaGetSymbolAddress((void**)&attn, g_attn);
    cudaGetSymbolAddress((void**)&opre, g_opre);
    cudaGetSymbolAddress((void**)&o,    g_o);
    cudaGetSymbolAddress((void**)&lin,  g_lin);

    // 1) shared LN1
    ln_kernel<<<TTOK, 128>>>(text,  nullptr, ln1_g, ln1_b, tn);
    ln_kernel<<<VTOK, 128>>>(video, nullptr, ln1_g, ln1_b, vn);

    // 2) projections (NT)
    mma_gemm<<<dim3(4, 32, 1), 128>>>(tn, EMBED, 0, Wq, EMBED, 0,
                                      q, EMBED, 0, bq, 1.0f, EMBED);
    mma_gemm<<<dim3(4, 6, 1), 128>>>(vn, EMBED, 0, Wk, EMBED, 0,
                                     k, EMBED, 0, bk, 1.0f, EMBED);
    mma_gemm<<<dim3(4, 6, 1), 128>>>(vn, EMBED, 0, Wv, EMBED, 0,
                                     v, EMBED, 0, bv, 1.0f, EMBED);

    // 3) transpose V for the attention GEMM
    transpose_kernel<<<dim3(16, 24), dim3(32, 8)>>>(v, vt);

    // 4) logits: S_h = Q_h @ K_h^T / 16, heads batched on z
    mma_gemm<<<dim3(6, 32, 2), 128>>>(
        q, EMBED, HDIM, k, EMBED, HDIM,
        s, VTOK, (long)TTOK * VTOK, nullptr, 1.0f / 16.0f, HDIM);

    // 5) per-video frame softmax
    softmax_kernel<<<(HEADS * TTOK * NV + 255) / 256, 256>>>(s, HEADS * TTOK * NV);

    // 6) attn_h = P_h @ V_h / 64 (mean over videos folded into alpha)
    mma_gemm<<<dim3(2, 32, 2), 128>>>(
        s, VTOK, (long)TTOK * VTOK, vt, VTOK, (long)HDIM * VTOK,
        attn, EMBED, HDIM, nullptr, 1.0f / 64.0f, VTOK);

    // 7) output projection + LN2
    mma_gemm<<<dim3(4, 32, 1), 128>>>(attn, EMBED, 0, Wo, EMBED, 0,
                                      opre, EMBED, 0, bo, 1.0f, EMBED);
    ln_kernel<<<TTOK, 128>>>(opre, nullptr, ln2_g, ln2_b, o);

    // 8) linear + residual + LN3
    mma_gemm<<<dim3(4, 32, 1), 128>>>(o, EMBED, 0, Wl, EMBED, 0,
                                      lin, EMBED, 0, bl, 1.0f, EMBED);
    ln_kernel<<<TTOK, 128>>>(o, lin, ln3_g, ln3_b, out);
}

// round 4
// speedup vs baseline: 2.2173x; 1.0344x over previous
#include <cuda_runtime.h>
#include <cstdint>

// ---------------------------------------------------------------------------
// XPool cross-modal attention, GB300 round 4: mma.sync tf32, 8-warp CTAs,
// K/V projections batched into one launch via pointer-difference z-strides.
// ---------------------------------------------------------------------------

#define EMBED 512
#define HEADS 2
#define HDIM  256
#define TTOK  4096
#define VTOK  768
#define FR    12
#define NV    64

// ------------------------------- scratch ----------------------------------
__device__ float g_tn  [TTOK*EMBED];
__device__ float g_vn  [VTOK*EMBED];
__device__ float g_q   [TTOK*EMBED];
__device__ float g_k   [VTOK*EMBED];
__device__ float g_v   [VTOK*EMBED];
__device__ float g_vt  [EMBED*VTOK];          // V transposed [512][768]
__device__ float g_s   [HEADS*TTOK*VTOK];     // logits/probs
__device__ float g_attn[TTOK*EMBED];
__device__ float g_opre[TTOK*EMBED];
__device__ float g_o   [TTOK*EMBED];
__device__ float g_lin [TTOK*EMBED];

__device__ __forceinline__ uint32_t f2tf32(float x) {
    uint32_t u;
    asm("cvt.rna.tf32.f32 %0, %1;" : "=r"(u) : "f"(x));
    return u;
}

// ---------------------------------------------------------------------------
// tf32 NT GEMM via mma.sync.m16n8k8.
// grid = (N/128, M/128, Z); 256 threads = 8 warps, each a 32x64 warp tile.
// z batches via element-offset strides (works for unrelated pointers too,
// since device address space is flat: pass (B2 - B1) etc).
// ---------------------------------------------------------------------------
__global__ __launch_bounds__(256) void mma_gemm(
    const float* __restrict__ A, int lda, long zA,
    const float* __restrict__ B, int ldb, long zB,
    float* __restrict__ C, int ldc, long zC,
    const float* __restrict__ bias, long zBias,
    float alpha, int K)
{
    // k-major tiles: As[buf][k][row], stride 132 -> bank = (4k + row) mod 32
    __shared__ uint32_t As[2][16][132];
    __shared__ uint32_t Bs[2][16][132];

    const int tid  = threadIdx.x;
    const int lane = tid & 31;
    const int warp = tid >> 5;
    const int wm   = (warp >> 1) * 32;   // warp row offset (4 row-warps x 32)
    const int wn   = (warp & 1) * 64;    // warp col offset (2 col-warps x 64)
    const int gid  = lane >> 2;          // 0..7
    const int tig  = lane & 3;           // 0..3

    const int bm = blockIdx.y * 128;
    const int bn = blockIdx.x * 128;
    A += (long)blockIdx.z * zA;
    B += (long)blockIdx.z * zB;
    C += (long)blockIdx.z * zC;
    if (bias) bias += (long)blockIdx.z * zBias;

    // producer mapping: 256 threads, row = tid&127, k-half = (tid>>7)*8
    const int prow = tid & 127;
    const int pkh  = (tid >> 7) * 8;
    const float* Ap = A + (size_t)(bm + prow) * lda + pkh;
    const float* Bp = B + (size_t)(bn + prow) * ldb + pkh;

    float acc[2][8][4];
#pragma unroll
    for (int mi = 0; mi < 2; mi++)
#pragma unroll
        for (int ni = 0; ni < 8; ni++)
#pragma unroll
            for (int r = 0; r < 4; r++) acc[mi][ni][r] = 0.0f;

    const int nsteps = K / 16;

    // stage 0
    {
        float4 a0 = *(const float4*)(Ap);
        float4 a1 = *(const float4*)(Ap + 4);
        float4 b0 = *(const float4*)(Bp);
        float4 b1 = *(const float4*)(Bp + 4);
        As[0][pkh+0][prow] = f2tf32(a0.x); As[0][pkh+1][prow] = f2tf32(a0.y);
        As[0][pkh+2][prow] = f2tf32(a0.z); As[0][pkh+3][prow] = f2tf32(a0.w);
        As[0][pkh+4][prow] = f2tf32(a1.x); As[0][pkh+5][prow] = f2tf32(a1.y);
        As[0][pkh+6][prow] = f2tf32(a1.z); As[0][pkh+7][prow] = f2tf32(a1.w);
        Bs[0][pkh+0][prow] = f2tf32(b0.x); Bs[0][pkh+1][prow] = f2tf32(b0.y);
        Bs[0][pkh+2][prow] = f2tf32(b0.z); Bs[0][pkh+3][prow] = f2tf32(b0.w);
        Bs[0][pkh+4][prow] = f2tf32(b1.x); Bs[0][pkh+5][prow] = f2tf32(b1.y);
        Bs[0][pkh+6][prow] = f2tf32(b1.z); Bs[0][pkh+7][prow] = f2tf32(b1.w);
    }
    __syncthreads();

#pragma unroll 1
    for (int step = 0; step < nsteps; step++) {
        const int cur = step & 1;
        const int nxt = cur ^ 1;
        const bool has_next = (step + 1) < nsteps;

        float4 a0, a1, b0, b1;
        if (has_next) {
            const float* ap = Ap + (step + 1) * 16;
            const float* bp = Bp + (step + 1) * 16;
            a0 = *(const float4*)(ap);
            a1 = *(const float4*)(ap + 4);
            b0 = *(const float4*)(bp);
            b1 = *(const float4*)(bp + 4);
        }

        // compute on buffer cur: 2 k-octets
#pragma unroll
        for (int kk = 0; kk < 2; kk++) {
            const int kb = kk * 8;
            uint32_t af[2][4];
#pragma unroll
            for (int mi = 0; mi < 2; mi++) {
                const int r0 = wm + mi * 16 + gid;
                af[mi][0] = As[cur][kb + tig    ][r0];
                af[mi][1] = As[cur][kb + tig    ][r0 + 8];
                af[mi][2] = As[cur][kb + tig + 4][r0];
                af[mi][3] = As[cur][kb + tig + 4][r0 + 8];
            }
            uint32_t bf[8][2];
#pragma unroll
            for (int ni = 0; ni < 8; ni++) {
                const int n0 = wn + ni * 8 + gid;
                bf[ni][0] = Bs[cur][kb + tig    ][n0];
                bf[ni][1] = Bs[cur][kb + tig + 4][n0];
            }
#pragma unroll
            for (int mi = 0; mi < 2; mi++)
#pragma unroll
                for (int ni = 0; ni < 8; ni++) {
                    asm("mma.sync.aligned.m16n8k8.row.col.f32.tf32.tf32.f32 "
                        "{%0,%1,%2,%3}, {%4,%5,%6,%7}, {%8,%9}, {%0,%1,%2,%3};"
                        : "+f"(acc[mi][ni][0]), "+f"(acc[mi][ni][1]),
                          "+f"(acc[mi][ni][2]), "+f"(acc[mi][ni][3])
                        : "r"(af[mi][0]), "r"(af[mi][1]),
                          "r"(af[mi][2]), "r"(af[mi][3]),
                          "r"(bf[ni][0]), "r"(bf[ni][1]));
                }
        }

        if (has_next) {
            As[nxt][pkh+0][prow] = f2tf32(a0.x); As[nxt][pkh+1][prow] = f2tf32(a0.y);
            As[nxt][pkh+2][prow] = f2tf32(a0.z); As[nxt][pkh+3][prow] = f2tf32(a0.w);
            As[nxt][pkh+4][prow] = f2tf32(a1.x); As[nxt][pkh+5][prow] = f2tf32(a1.y);
            As[nxt][pkh+6][prow] = f2tf32(a1.z); As[nxt][pkh+7][prow] = f2tf32(a1.w);
            Bs[nxt][pkh+0][prow] = f2tf32(b0.x); Bs[nxt][pkh+1][prow] = f2tf32(b0.y);
            Bs[nxt][pkh+2][prow] = f2tf32(b0.z); Bs[nxt][pkh+3][prow] = f2tf32(b0.w);
            Bs[nxt][pkh+4][prow] = f2tf32(b1.x); Bs[nxt][pkh+5][prow] = f2tf32(b1.y);
            Bs[nxt][pkh+6][prow] = f2tf32(b1.z); Bs[nxt][pkh+7][prow] = f2tf32(b1.w);
            __syncthreads();
        }
    }

    // epilogue: c0,c1 at (row, 2*tig), c2,c3 at (row+8, 2*tig)
#pragma unroll
    for (int mi = 0; mi < 2; mi++) {
        const int r0 = bm + wm + mi * 16 + gid;
#pragma unroll
        for (int ni = 0; ni < 8; ni++) {
            const int c0 = bn + wn + ni * 8 + tig * 2;
            float bx = 0.0f, by = 0.0f;
            if (bias) { bx = bias[c0]; by = bias[c0 + 1]; }
            float2 v0, v1;
            v0.x = alpha * acc[mi][ni][0] + bx;
            v0.y = alpha * acc[mi][ni][1] + by;
            v1.x = alpha * acc[mi][ni][2] + bx;
            v1.y = alpha * acc[mi][ni][3] + by;
            *(float2*)(C + (size_t)r0 * ldc + c0)       = v0;
            *(float2*)(C + (size_t)(r0 + 8) * ldc + c0) = v1;
        }
    }
}

// ---------------------------------------------------------------------------
// LayerNorm (optionally fused residual add). One block per row.
// ---------------------------------------------------------------------------
__global__ __launch_bounds__(128) void ln_kernel(
    const float* __restrict__ x, const float* __restrict__ addx,
    const float* __restrict__ g, const float* __restrict__ b,
    float* __restrict__ out)
{
    const int row = blockIdx.x;
    const int t = threadIdx.x;
    const float* xr = x + (size_t)row * EMBED;

    float v[4];
#pragma unroll
    for (int i = 0; i < 4; i++) {
        float val = xr[t + i * 128];
        if (addx) val += addx[(size_t)row * EMBED + t + i * 128];
        v[i] = val;
    }
    float s  = v[0] + v[1] + v[2] + v[3];
    float s2 = v[0]*v[0] + v[1]*v[1] + v[2]*v[2] + v[3]*v[3];
#pragma unroll
    for (int o = 16; o > 0; o >>= 1) {
        s  += __shfl_xor_sync(0xffffffffu, s,  o);
        s2 += __shfl_xor_sync(0xffffffffu, s2, o);
    }
    __shared__ float ss[4], ss2[4];
    const int w = t >> 5, l = t & 31;
    if (l == 0) { ss[w] = s; ss2[w] = s2; }
    __syncthreads();
    s  = ss[0] + ss[1] + ss[2] + ss[3];
    s2 = ss2[0] + ss2[1] + ss2[2] + ss2[3];

    const float mu   = s * (1.0f / EMBED);
    const float var  = s2 * (1.0f / EMBED) - mu * mu;
    const float rstd = rsqrtf(var + 1e-5f);
#pragma unroll
    for (int i = 0; i < 4; i++) {
        const int c = t + i * 128;
        out[(size_t)row * EMBED + c] = (v[i] - mu) * rstd * g[c] + b[c];
    }
}

// ---------------------------------------------------------------------------
// Per-(video,head,token) softmax over 12 contiguous frames.
// ---------------------------------------------------------------------------
__global__ __launch_bounds__(256) void softmax_kernel(float* __restrict__ S, int ngroups)
{
    const int g = blockIdx.x * blockDim.x + threadIdx.x;
    if (g >= ngroups) return;
    float* p = S + (size_t)g * FR;
    float v[FR];
    float m = -3.0e38f;
#pragma unroll
    for (int i = 0; i < FR; i++) { v[i] = p[i]; m = fmaxf(m, v[i]); }
    float sum = 0.0f;
#pragma unroll
    for (int i = 0; i < FR; i++) { v[i] = __expf(v[i] - m); sum += v[i]; }
    const float inv = 1.0f / sum;
#pragma unroll
    for (int i = 0; i < FR; i++) p[i] = v[i] * inv;
}

// ---------------------------------------------------------------------------
// Transpose V [768][512] -> Vt [512][768]
// ---------------------------------------------------------------------------
__global__ __launch_bounds__(256) void transpose_kernel(
    const float* __restrict__ in, float* __restrict__ out)
{
    __shared__ float t[32][33];
    const int x  = blockIdx.x * 32 + threadIdx.x;   // col in V (0..511)
    const int y0 = blockIdx.y * 32;                 // row in V (0..767)
#pragma unroll
    for (int i = threadIdx.y; i < 32; i += 8)
        t[i][threadIdx.x] = in[(size_t)(y0 + i) * EMBED + x];
    __syncthreads();
    const int ox  = y0 + threadIdx.x;               // col in Vt (0..767)
    const int oy0 = blockIdx.x * 32;                // row in Vt (0..511)
#pragma unroll
    for (int i = threadIdx.y; i < 32; i += 8)
        out[(size_t)(oy0 + i) * VTOK + ox] = t[threadIdx.x][i];
}

// ---------------------------------------------------------------------------
extern "C" void kernel_launch(void* const* d_in, const int* in_sizes, int n_in,
                              void* d_out, int out_size)
{
    const float* text  = (const float*)d_in[0];
    const float* video = (const float*)d_in[1];
    const float* ln1_g = (const float*)d_in[2];
    const float* ln1_b = (const float*)d_in[3];
    const float* Wq = (const float*)d_in[4];
    const float* bq = (const float*)d_in[5];
    const float* Wk = (const float*)d_in[6];
    const float* bk = (const float*)d_in[7];
    const float* Wv = (const float*)d_in[8];
    const float* bv = (const float*)d_in[9];
    const float* Wo = (const float*)d_in[10];
    const float* bo = (const float*)d_in[11];
    const float* Wl = (const float*)d_in[12];
    const float* bl = (const float*)d_in[13];
    const float* ln2_g = (const float*)d_in[14];
    const float* ln2_b = (const float*)d_in[15];
    const float* ln3_g = (const float*)d_in[16];
    const float* ln3_b = (const float*)d_in[17];
    float* out = (float*)d_out;

    float *tn, *vn, *q, *k, *v, *vt, *s, *attn, *opre, *o, *lin;
    cudaGetSymbolAddress((void**)&tn,   g_tn);
    cudaGetSymbolAddress((void**)&vn,   g_vn);
    cudaGetSymbolAddress((void**)&q,    g_q);
    cudaGetSymbolAddress((void**)&k,    g_k);
    cudaGetSymbolAddress((void**)&v,    g_v);
    cudaGetSymbolAddress((void**)&vt,   g_vt);
    cudaGetSymbolAddress((void**)&s,    g_s);
    cudaGetSymbolAddress((void**)&attn, g_attn);
    cudaGetSymbolAddress((void**)&opre, g_opre);
    cudaGetSymbolAddress((void**)&o,    g_o);
    cudaGetSymbolAddress((void**)&lin,  g_lin);

    // 1) shared LN1
    ln_kernel<<<TTOK, 128>>>(text,  nullptr, ln1_g, ln1_b, tn);
    ln_kernel<<<VTOK, 128>>>(video, nullptr, ln1_g, ln1_b, vn);

    // 2) projections (NT). K and V batched on z via pointer-diff strides.
    mma_gemm<<<dim3(4, 32, 1), 256>>>(tn, EMBED, 0, Wq, EMBED, 0,
                                      q, EMBED, 0, bq, 0, 1.0f, EMBED);
    mma_gemm<<<dim3(4, 6, 2), 256>>>(vn, EMBED, 0,
                                     Wk, EMBED, (long)(Wv - Wk),
                                     k, EMBED, (long)(v - k),
                                     bk, (long)(bv - bk), 1.0f, EMBED);

    // 3) transpose V for the attention GEMM
    transpose_kernel<<<dim3(16, 24), dim3(32, 8)>>>(v, vt);

    // 4) logits: S_h = Q_h @ K_h^T / 16, heads batched on z
    mma_gemm<<<dim3(6, 32, 2), 256>>>(
        q, EMBED, HDIM, k, EMBED, HDIM,
        s, VTOK, (long)TTOK * VTOK, nullptr, 0, 1.0f / 16.0f, HDIM);

    // 5) per-video frame softmax
    softmax_kernel<<<(HEADS * TTOK * NV + 255) / 256, 256>>>(s, HEADS * TTOK * NV);

    // 6) attn_h = P_h @ V_h / 64 (mean over videos folded into alpha)
    mma_gemm<<<dim3(2, 32, 2), 256>>>(
        s, VTOK, (long)TTOK * VTOK, vt, VTOK, (long)HDIM * VTOK,
        attn, EMBED, HDIM, nullptr, 0, 1.0f / 64.0f, VTOK);

    // 7) output projection + LN2
    mma_gemm<<<dim3(4, 32, 1), 256>>>(attn, EMBED, 0, Wo, EMBED, 0,
                                      opre, EMBED, 0, bo, 0, 1.0f, EMBED);
    ln_kernel<<<TTOK, 128>>>(opre, nullptr, ln2_g, ln2_b, o);

    // 8) linear + residual + LN3
    mma_gemm<<<dim3(4, 32, 1), 256>>>(o, EMBED, 0, Wl, EMBED, 0,
                                      lin, EMBED, 0, bl, 0, 1.0f, EMBED);
    ln_kernel<<<TTOK, 128>>>(o, lin, ln3_g, ln3_b, out);
}

// round 5
// speedup vs baseline: 2.5981x; 1.1718x over previous
#include <cuda_runtime.h>
#include <cstdint>

// ---------------------------------------------------------------------------
// XPool cross-modal attention, GB300 round 5: mma.sync tf32.
//  - smem stride 136 (conflict-free fragment LDS: bank = 8k+row mod 32)
//  - __launch_bounds__(256,2): 2 CTAs/SM co-residency
//  - Q/K/V projections merged into one launch (z = 0,1,2)
// ---------------------------------------------------------------------------

#define EMBED 512
#define HEADS 2
#define HDIM  256
#define TTOK  4096
#define VTOK  768
#define FR    12
#define NV    64

// ------------------------------- scratch ----------------------------------
__device__ float g_tn  [TTOK*EMBED];
__device__ float g_vn  [VTOK*EMBED];
__device__ float g_q   [TTOK*EMBED];
__device__ float g_k   [VTOK*EMBED];
__device__ float g_v   [VTOK*EMBED];
__device__ float g_vt  [EMBED*VTOK];          // V transposed [512][768]
__device__ float g_s   [HEADS*TTOK*VTOK];     // logits/probs
__device__ float g_attn[TTOK*EMBED];
__device__ float g_opre[TTOK*EMBED];
__device__ float g_o   [TTOK*EMBED];
__device__ float g_lin [TTOK*EMBED];

__device__ __forceinline__ uint32_t f2tf32(float x) {
    uint32_t u;
    asm("cvt.rna.tf32.f32 %0, %1;" : "=r"(u) : "f"(x));
    return u;
}

// k-major smem tiles with stride 136 words: bank = (8k + row) mod 32.
#define SST 136

// ---------------------------------------------------------------------------
// Core 128x128 NT tf32 GEMM tile body. 256 threads = 8 warps (4x2 of 32x64).
// C[i,j] = alpha * sum_k A[i,k]*B[j,k] (+ bias[j]).
// ---------------------------------------------------------------------------
__device__ __forceinline__ void gemm_tile_body(
    const float* __restrict__ A, int lda,
    const float* __restrict__ B, int ldb,
    float* __restrict__ C, int ldc,
    const float* __restrict__ bias,
    float alpha, int K, int bm, int bn,
    uint32_t (*As)[16][SST], uint32_t (*Bs)[16][SST])
{
    const int tid  = threadIdx.x;
    const int lane = tid & 31;
    const int warp = tid >> 5;
    const int wm   = (warp >> 1) * 32;   // 4 row-warps x 32
    const int wn   = (warp & 1) * 64;    // 2 col-warps x 64
    const int gid  = lane >> 2;          // 0..7
    const int tig  = lane & 3;           // 0..3

    const int prow = tid & 127;
    const int pkh  = (tid >> 7) * 8;
    const float* Ap = A + (size_t)(bm + prow) * lda + pkh;
    const float* Bp = B + (size_t)(bn + prow) * ldb + pkh;

    float acc[2][8][4];
#pragma unroll
    for (int mi = 0; mi < 2; mi++)
#pragma unroll
        for (int ni = 0; ni < 8; ni++)
#pragma unroll
            for (int r = 0; r < 4; r++) acc[mi][ni][r] = 0.0f;

    const int nsteps = K / 16;

    {
        float4 a0 = *(const float4*)(Ap);
        float4 a1 = *(const float4*)(Ap + 4);
        float4 b0 = *(const float4*)(Bp);
        float4 b1 = *(const float4*)(Bp + 4);
        As[0][pkh+0][prow] = f2tf32(a0.x); As[0][pkh+1][prow] = f2tf32(a0.y);
        As[0][pkh+2][prow] = f2tf32(a0.z); As[0][pkh+3][prow] = f2tf32(a0.w);
        As[0][pkh+4][prow] = f2tf32(a1.x); As[0][pkh+5][prow] = f2tf32(a1.y);
        As[0][pkh+6][prow] = f2tf32(a1.z); As[0][pkh+7][prow] = f2tf32(a1.w);
        Bs[0][pkh+0][prow] = f2tf32(b0.x); Bs[0][pkh+1][prow] = f2tf32(b0.y);
        Bs[0][pkh+2][prow] = f2tf32(b0.z); Bs[0][pkh+3][prow] = f2tf32(b0.w);
        Bs[0][pkh+4][prow] = f2tf32(b1.x); Bs[0][pkh+5][prow] = f2tf32(b1.y);
        Bs[0][pkh+6][prow] = f2tf32(b1.z); Bs[0][pkh+7][prow] = f2tf32(b1.w);
    }
    __syncthreads();

#pragma unroll 1
    for (int step = 0; step < nsteps; step++) {
        const int cur = step & 1;
        const int nxt = cur ^ 1;
        const bool has_next = (step + 1) < nsteps;

        float4 a0, a1, b0, b1;
        if (has_next) {
            const float* ap = Ap + (step + 1) * 16;
            const float* bp = Bp + (step + 1) * 16;
            a0 = *(const float4*)(ap);
            a1 = *(const float4*)(ap + 4);
            b0 = *(const float4*)(bp);
            b1 = *(const float4*)(bp + 4);
        }

#pragma unroll
        for (int kk = 0; kk < 2; kk++) {
            const int kb = kk * 8;
            uint32_t af[2][4];
#pragma unroll
            for (int mi = 0; mi < 2; mi++) {
                const int r0 = wm + mi * 16 + gid;
                af[mi][0] = As[cur][kb + tig    ][r0];
                af[mi][1] = As[cur][kb + tig    ][r0 + 8];
                af[mi][2] = As[cur][kb + tig + 4][r0];
                af[mi][3] = As[cur][kb + tig + 4][r0 + 8];
            }
            uint32_t bf[8][2];
#pragma unroll
            for (int ni = 0; ni < 8; ni++) {
                const int n0 = wn + ni * 8 + gid;
                bf[ni][0] = Bs[cur][kb + tig    ][n0];
                bf[ni][1] = Bs[cur][kb + tig + 4][n0];
            }
#pragma unroll
            for (int mi = 0; mi < 2; mi++)
#pragma unroll
                for (int ni = 0; ni < 8; ni++) {
                    asm("mma.sync.aligned.m16n8k8.row.col.f32.tf32.tf32.f32 "
                        "{%0,%1,%2,%3}, {%4,%5,%6,%7}, {%8,%9}, {%0,%1,%2,%3};"
                        : "+f"(acc[mi][ni][0]), "+f"(acc[mi][ni][1]),
                          "+f"(acc[mi][ni][2]), "+f"(acc[mi][ni][3])
                        : "r"(af[mi][0]), "r"(af[mi][1]),
                          "r"(af[mi][2]), "r"(af[mi][3]),
                          "r"(bf[ni][0]), "r"(bf[ni][1]));
                }
        }

        if (has_next) {
            As[nxt][pkh+0][prow] = f2tf32(a0.x); As[nxt][pkh+1][prow] = f2tf32(a0.y);
            As[nxt][pkh+2][prow] = f2tf32(a0.z); As[nxt][pkh+3][prow] = f2tf32(a0.w);
            As[nxt][pkh+4][prow] = f2tf32(a1.x); As[nxt][pkh+5][prow] = f2tf32(a1.y);
            As[nxt][pkh+6][prow] = f2tf32(a1.z); As[nxt][pkh+7][prow] = f2tf32(a1.w);
            Bs[nxt][pkh+0][prow] = f2tf32(b0.x); Bs[nxt][pkh+1][prow] = f2tf32(b0.y);
            Bs[nxt][pkh+2][prow] = f2tf32(b0.z); Bs[nxt][pkh+3][prow] = f2tf32(b0.w);
            Bs[nxt][pkh+4][prow] = f2tf32(b1.x); Bs[nxt][pkh+5][prow] = f2tf32(b1.y);
            Bs[nxt][pkh+6][prow] = f2tf32(b1.z); Bs[nxt][pkh+7][prow] = f2tf32(b1.w);
            __syncthreads();
        }
    }

#pragma unroll
    for (int mi = 0; mi < 2; mi++) {
        const int r0 = bm + wm + mi * 16 + gid;
#pragma unroll
        for (int ni = 0; ni < 8; ni++) {
            const int c0 = bn + wn + ni * 8 + tig * 2;
            float bx = 0.0f, by = 0.0f;
            if (bias) { bx = bias[c0]; by = bias[c0 + 1]; }
            float2 v0, v1;
            v0.x = alpha * acc[mi][ni][0] + bx;
            v0.y = alpha * acc[mi][ni][1] + by;
            v1.x = alpha * acc[mi][ni][2] + bx;
            v1.y = alpha * acc[mi][ni][3] + by;
            *(float2*)(C + (size_t)r0 * ldc + c0)       = v0;
            *(float2*)(C + (size_t)(r0 + 8) * ldc + c0) = v1;
        }
    }
}

// Generic z-batched NT GEMM (z strides may be pointer differences).
__global__ __launch_bounds__(256, 2) void mma_gemm(
    const float* __restrict__ A, int lda, long zA,
    const float* __restrict__ B, int ldb, long zB,
    float* __restrict__ C, int ldc, long zC,
    const float* __restrict__ bias, long zBias,
    float alpha, int K)
{
    __shared__ uint32_t As[2][16][SST];
    __shared__ uint32_t Bs[2][16][SST];
    A += (long)blockIdx.z * zA;
    B += (long)blockIdx.z * zB;
    C += (long)blockIdx.z * zC;
    if (bias) bias += (long)blockIdx.z * zBias;
    gemm_tile_body(A, lda, B, ldb, C, ldc, bias, alpha, K,
                   blockIdx.y * 128, blockIdx.x * 128, As, Bs);
}

// All three input projections in one launch: z=0 Q (M=4096), z=1 K, z=2 V
// (M=768; CTAs with bm >= 768 exit immediately).
__global__ __launch_bounds__(256, 2) void proj3_gemm(
    const float* __restrict__ tn, const float* __restrict__ vn,
    const float* __restrict__ Wq, const float* __restrict__ Wk,
    const float* __restrict__ Wv,
    const float* __restrict__ bq, const float* __restrict__ bk,
    const float* __restrict__ bv,
    float* __restrict__ q, float* __restrict__ k, float* __restrict__ v)
{
    __shared__ uint32_t As[2][16][SST];
    __shared__ uint32_t Bs[2][16][SST];
    const int z  = blockIdx.z;
    const int bm = blockIdx.y * 128;
    if (z > 0 && bm >= VTOK) return;
    const float* A = (z == 0) ? tn : vn;
    const float* B = (z == 0) ? Wq : (z == 1) ? Wk : Wv;
    const float* bias = (z == 0) ? bq : (z == 1) ? bk : bv;
    float* C = (z == 0) ? q : (z == 1) ? k : v;
    gemm_tile_body(A, EMBED, B, EMBED, C, EMBED, bias, 1.0f, EMBED,
                   bm, blockIdx.x * 128, As, Bs);
}

// ---------------------------------------------------------------------------
// LayerNorm (optionally fused residual add). One block per row.
// ---------------------------------------------------------------------------
__global__ __launch_bounds__(128) void ln_kernel(
    const float* __restrict__ x, const float* __restrict__ addx,
    const float* __restrict__ g, const float* __restrict__ b,
    float* __restrict__ out)
{
    const int row = blockIdx.x;
    const int t = threadIdx.x;
    const float* xr = x + (size_t)row * EMBED;

    float v[4];
#pragma unroll
    for (int i = 0; i < 4; i++) {
        float val = xr[t + i * 128];
        if (addx) val += addx[(size_t)row * EMBED + t + i * 128];
        v[i] = val;
    }
    float s  = v[0] + v[1] + v[2] + v[3];
    float s2 = v[0]*v[0] + v[1]*v[1] + v[2]*v[2] + v[3]*v[3];
#pragma unroll
    for (int o = 16; o > 0; o >>= 1) {
        s  += __shfl_xor_sync(0xffffffffu, s,  o);
        s2 += __shfl_xor_sync(0xffffffffu, s2, o);
    }
    __shared__ float ss[4], ss2[4];
    const int w = t >> 5, l = t & 31;
    if (l == 0) { ss[w] = s; ss2[w] = s2; }
    __syncthreads();
    s  = ss[0] + ss[1] + ss[2] + ss[3];
    s2 = ss2[0] + ss2[1] + ss2[2] + ss2[3];

    const float mu   = s * (1.0f / EMBED);
    const float var  = s2 * (1.0f / EMBED) - mu * mu;
    const float rstd = rsqrtf(var + 1e-5f);
#pragma unroll
    for (int i = 0; i < 4; i++) {
        const int c = t + i * 128;
        out[(size_t)row * EMBED + c] = (v[i] - mu) * rstd * g[c] + b[c];
    }
}

// ---------------------------------------------------------------------------
// Per-(video,head,token) softmax over 12 contiguous frames.
// ---------------------------------------------------------------------------
__global__ __launch_bounds__(256) void softmax_kernel(float* __restrict__ S, int ngroups)
{
    const int g = blockIdx.x * blockDim.x + threadIdx.x;
    if (g >= ngroups) return;
    float* p = S + (size_t)g * FR;
    float v[FR];
    float m = -3.0e38f;
#pragma unroll
    for (int i = 0; i < FR; i++) { v[i] = p[i]; m = fmaxf(m, v[i]); }
    float sum = 0.0f;
#pragma unroll
    for (int i = 0; i < FR; i++) { v[i] = __expf(v[i] - m); sum += v[i]; }
    const float inv = 1.0f / sum;
#pragma unroll
    for (int i = 0; i < FR; i++) p[i] = v[i] * inv;
}

// ---------------------------------------------------------------------------
// Transpose V [768][512] -> Vt [512][768]
// ---------------------------------------------------------------------------
__global__ __launch_bounds__(256) void transpose_kernel(
    const float* __restrict__ in, float* __restrict__ out)
{
    __shared__ float t[32][33];
    const int x  = blockIdx.x * 32 + threadIdx.x;
    const int y0 = blockIdx.y * 32;
#pragma unroll
    for (int i = threadIdx.y; i < 32; i += 8)
        t[i][threadIdx.x] = in[(size_t)(y0 + i) * EMBED + x];
    __syncthreads();
    const int ox  = y0 + threadIdx.x;
    const int oy0 = blockIdx.x * 32;
#pragma unroll
    for (int i = threadIdx.y; i < 32; i += 8)
        out[(size_t)(oy0 + i) * VTOK + ox] = t[threadIdx.x][i];
}

// ---------------------------------------------------------------------------
extern "C" void kernel_launch(void* const* d_in, const int* in_sizes, int n_in,
                              void* d_out, int out_size)
{
    const float* text  = (const float*)d_in[0];
    const float* video = (const float*)d_in[1];
    const float* ln1_g = (const float*)d_in[2];
    const float* ln1_b = (const float*)d_in[3];
    const float* Wq = (const float*)d_in[4];
    const float* bq = (const float*)d_in[5];
    const float* Wk = (const float*)d_in[6];
    const float* bk = (const float*)d_in[7];
    const float* Wv = (const float*)d_in[8];
    const float* bv = (const float*)d_in[9];
    const float* Wo = (const float*)d_in[10];
    const float* bo = (const float*)d_in[11];
    const float* Wl = (const float*)d_in[12];
    const float* bl = (const float*)d_in[13];
    const float* ln2_g = (const float*)d_in[14];
    const float* ln2_b = (const float*)d_in[15];
    const float* ln3_g = (const float*)d_in[16];
    const float* ln3_b = (const float*)d_in[17];
    float* out = (float*)d_out;

    float *tn, *vn, *q, *k, *v, *vt, *s, *attn, *opre, *o, *lin;
    cudaGetSymbolAddress((void**)&tn,   g_tn);
    cudaGetSymbolAddress((void**)&vn,   g_vn);
    cudaGetSymbolAddress((void**)&q,    g_q);
    cudaGetSymbolAddress((void**)&k,    g_k);
    cudaGetSymbolAddress((void**)&v,    g_v);
    cudaGetSymbolAddress((void**)&vt,   g_vt);
    cudaGetSymbolAddress((void**)&s,    g_s);
    cudaGetSymbolAddress((void**)&attn, g_attn);
    cudaGetSymbolAddress((void**)&opre, g_opre);
    cudaGetSymbolAddress((void**)&o,    g_o);
    cudaGetSymbolAddress((void**)&lin,  g_lin);

    // 1) shared LN1
    ln_kernel<<<TTOK, 128>>>(text,  nullptr, ln1_g, ln1_b, tn);
    ln_kernel<<<VTOK, 128>>>(video, nullptr, ln1_g, ln1_b, vn);

    // 2) Q/K/V projections in one launch
    proj3_gemm<<<dim3(4, 32, 3), 256>>>(tn, vn, Wq, Wk, Wv, bq, bk, bv, q, k, v);

    // 3) transpose V
    transpose_kernel<<<dim3(16, 24), dim3(32, 8)>>>(v, vt);

    // 4) logits: S_h = Q_h @ K_h^T / 16, heads on z
    mma_gemm<<<dim3(6, 32, 2), 256>>>(
        q, EMBED, HDIM, k, EMBED, HDIM,
        s, VTOK, (long)TTOK * VTOK, nullptr, 0, 1.0f / 16.0f, HDIM);

    // 5) per-video frame softmax
    softmax_kernel<<<(HEADS * TTOK * NV + 255) / 256, 256>>>(s, HEADS * TTOK * NV);

    // 6) attn_h = P_h @ V_h / 64
    mma_gemm<<<dim3(2, 32, 2), 256>>>(
        s, VTOK, (long)TTOK * VTOK, vt, VTOK, (long)HDIM * VTOK,
        attn, EMBED, HDIM, nullptr, 0, 1.0f / 64.0f, VTOK);

    // 7) output projection + LN2
    mma_gemm<<<dim3(4, 32, 1), 256>>>(attn, EMBED, 0, Wo, EMBED, 0,
                                      opre, EMBED, 0, bo, 0, 1.0f, EMBED);
    ln_kernel<<<TTOK, 128>>>(opre, nullptr, ln2_g, ln2_b, o);

    // 8) linear + residual + LN3
    mma_gemm<<<dim3(4, 32, 1), 256>>>(o, EMBED, 0, Wl, EMBED, 0,
                                      lin, EMBED, 0, bl, 0, 1.0f, EMBED);
    ln_kernel<<<TTOK, 128>>>(o, lin, ln3_g, ln3_b, out);
}